// round 13
// baseline (speedup 1.0000x reference)
#include <cuda_runtime.h>
#include <cstdint>

#define SLEN 2048
#define EDIM 512
#define HDIM 256
#define NTAG 32
#define START_TAG 30
#define STOP_TAG 31
#define NEGV (-10000.0f)
#define HP 272   // padded per-buffer h stride: 4 chunks x (64+4) floats
#define CL 16    // cluster size (CTAs per direction)

// ---------------- scratch (device globals; no runtime alloc) ----------------
__device__ float g_px[2][SLEN * 4 * HDIM];
__device__ float g_h[2][SLEN * HDIM];
__device__ float g_feats[SLEN * NTAG];
__device__ float g_fv[SLEN * NTAG];            // fv at ENTRY of step t
__device__ unsigned char g_bp[SLEN * NTAG];    // backpointers
__device__ int g_last;                         // terminal argmax

// ---------------- K1: px = embed[sent] @ W_ih^T + b (gather fused) ----------
#define BM 128
#define BN 128
#define BK 16
#define SPAD 132

__global__ __launch_bounds__(256) void px_gemm_kernel(
    const int* __restrict__ sent, const float* __restrict__ embed,
    const float* __restrict__ w_f, const float* __restrict__ b_f,
    const float* __restrict__ w_b, const float* __restrict__ b_b)
{
    int dir = blockIdx.z;
    const float* W = dir ? w_b : w_f;
    const float* bias = dir ? b_b : b_f;
    float* C = g_px[dir];

    __shared__ float As[BK * SPAD];
    __shared__ float Bs[BK * SPAD];
    __shared__ int sidx[BM];

    int tid = threadIdx.x;
    int m_block = blockIdx.x * BM;
    int n_block = blockIdx.y * BN;

    if (tid < BM) sidx[tid] = sent[m_block + tid];

    int lm = tid >> 2;
    int lk4 = (tid & 3) * 4;
    int ty = tid >> 4;
    int tx = tid & 15;
    int m0 = ty * 8, n0 = tx * 8;

    __syncthreads();
    int arow0 = sidx[lm];
    int arow1 = sidx[lm + 64];

    float acc[8][8];
#pragma unroll
    for (int i = 0; i < 8; i++)
#pragma unroll
        for (int j = 0; j < 8; j++) acc[i][j] = 0.f;

    for (int kt = 0; kt < EDIM; kt += BK) {
#pragma unroll
        for (int h = 0; h < 2; h++) {
            int m = lm + h * 64;
            int arow = h ? arow1 : arow0;
            float4 a = *(const float4*)(embed + (size_t)arow * EDIM + kt + lk4);
            As[(lk4 + 0) * SPAD + m] = a.x;
            As[(lk4 + 1) * SPAD + m] = a.y;
            As[(lk4 + 2) * SPAD + m] = a.z;
            As[(lk4 + 3) * SPAD + m] = a.w;
            float4 b = *(const float4*)(W + (size_t)(n_block + m) * EDIM + kt + lk4);
            Bs[(lk4 + 0) * SPAD + m] = b.x;
            Bs[(lk4 + 1) * SPAD + m] = b.y;
            Bs[(lk4 + 2) * SPAD + m] = b.z;
            Bs[(lk4 + 3) * SPAD + m] = b.w;
        }
        __syncthreads();
#pragma unroll
        for (int k = 0; k < BK; k++) {
            float ar[8], br[8];
            *(float4*)(ar + 0) = *(const float4*)(&As[k * SPAD + m0 + 0]);
            *(float4*)(ar + 4) = *(const float4*)(&As[k * SPAD + m0 + 4]);
            *(float4*)(br + 0) = *(const float4*)(&Bs[k * SPAD + n0 + 0]);
            *(float4*)(br + 4) = *(const float4*)(&Bs[k * SPAD + n0 + 4]);
#pragma unroll
            for (int i = 0; i < 8; i++)
#pragma unroll
                for (int j = 0; j < 8; j++) acc[i][j] += ar[i] * br[j];
        }
        __syncthreads();
    }
#pragma unroll
    for (int i = 0; i < 8; i++) {
        int row = m_block + m0 + i;
#pragma unroll
        for (int j4 = 0; j4 < 8; j4 += 4) {
            int n = n_block + n0 + j4;
            float4 v;
            v.x = acc[i][j4 + 0] + bias[n + 0];
            v.y = acc[i][j4 + 1] + bias[n + 1];
            v.z = acc[i][j4 + 2] + bias[n + 2];
            v.w = acc[i][j4 + 3] + bias[n + 3];
            *(float4*)(C + row * (4 * HDIM) + n) = v;
        }
    }
}

// ---------------- K2: recurrent LSTM — 16-CTA cluster per direction ---------
// (unchanged from R11/R12 — best known)
__device__ __forceinline__ float fast_sigmoid(float x) {
    return __fdividef(1.f, 1.f + __expf(-x));
}
__device__ __forceinline__ float fast_tanh(float x) {
    return 1.f - __fdividef(2.f, __expf(2.f * x) + 1.f);
}
__device__ __forceinline__ void wait_mbar(uint32_t addr, uint32_t parity) {
    uint32_t done;
    asm volatile(
        "{\n .reg .pred P;\n"
        " mbarrier.try_wait.parity.acquire.cluster.shared::cta.b64 P, [%1], %2;\n"
        " selp.b32 %0, 1, 0, P;\n}"
        : "=r"(done) : "r"(addr), "r"(parity) : "memory");
    while (!done) {
        asm volatile(
            "{\n .reg .pred P;\n"
            " mbarrier.try_wait.parity.acquire.cluster.shared::cta.b64 P, [%1], %2, 0x989680;\n"
            " selp.b32 %0, 1, 0, P;\n}"
            : "=r"(done) : "r"(addr), "r"(parity) : "memory");
    }
}

__global__ void __cluster_dims__(CL, 1, 1) __launch_bounds__(256, 1) lstm_kernel(
    const float* __restrict__ w_hh_f, const float* __restrict__ w_hh_b,
    const float* __restrict__ h0, const float* __restrict__ c0)
{
    __shared__ __align__(16) float hbuf[2 * HP];
    __shared__ __align__(16) float red[2][256];
    __shared__ __align__(8) unsigned long long mbars[2];

    int tid = threadIdx.x;
    int dir = blockIdx.x >> 4;
    uint32_t crank;
    asm("mov.u32 %0, %%cluster_ctarank;" : "=r"(crank));
    int base_u = crank * 16;

    const float* Whh = dir ? w_hh_b : w_hh_f;
    const float* px = g_px[dir];
    float* hout = g_h[dir];

    int q = tid >> 6;
    int lr = tid & 63;
    int gr = ((lr >> 4) << 8) + base_u + (lr & 15);

    uint64_t wreg[32];
    {
        const uint64_t* ws = (const uint64_t*)(Whh + (size_t)gr * 256 + q * 64);
#pragma unroll
        for (int j = 0; j < 32; j++) wreg[j] = ws[j];
    }

    hbuf[tid + (tid >> 6) * 4] = h0[dir * HDIM + tid];
    int u = base_u + (tid & 15);
    float c_reg = (tid < 32) ? c0[dir * HDIM + u] : 0.f;

    uint32_t hbuf_sa = (uint32_t)__cvta_generic_to_shared(hbuf);
    uint32_t mbar_sa = (uint32_t)__cvta_generic_to_shared(mbars);

    if (tid == 0) {
        asm volatile("mbarrier.init.shared.b64 [%0], 16;" :: "r"(mbar_sa) : "memory");
        asm volatile("mbarrier.init.shared.b64 [%0], 16;" :: "r"(mbar_sa + 8) : "memory");
        asm volatile("fence.mbarrier_init.release.cluster;" ::: "memory");
    }

    uint32_t rstore0[8], rstore1[8];
    uint32_t rmb0 = 0, rmb1 = 0;
    if (tid < 32) {
        int slot = u + (u >> 6) * 4;
        uint32_t d0 = hbuf_sa + ((0 * HP + slot) << 2);
        uint32_t d1 = hbuf_sa + ((1 * HP + slot) << 2);
        int rbase = (tid >> 4) * 8;
#pragma unroll
        for (int rr = 0; rr < 8; rr++) {
            asm("mapa.shared::cluster.u32 %0, %1, %2;" : "=r"(rstore0[rr]) : "r"(d0), "r"(rbase + rr));
            asm("mapa.shared::cluster.u32 %0, %1, %2;" : "=r"(rstore1[rr]) : "r"(d1), "r"(rbase + rr));
        }
        if (tid < 16) {
            asm("mapa.shared::cluster.u32 %0, %1, %2;" : "=r"(rmb0) : "r"(mbar_sa), "r"(tid));
            asm("mapa.shared::cluster.u32 %0, %1, %2;" : "=r"(rmb1) : "r"(mbar_sa + 8), "r"(tid));
        }
    }

    __syncthreads();
    asm volatile("barrier.cluster.arrive.aligned;" ::: "memory");
    asm volatile("barrier.cluster.wait.aligned;" ::: "memory");

    float pxi = 0.f, pxf = 0.f, pxg = 0.f, pxo = 0.f;
    if (tid < 32) {
        const float* prow = px + (size_t)(dir ? SLEN - 1 : 0) * 1024;
        pxi = __ldg(prow + u);
        pxf = __ldg(prow + 256 + u);
        pxg = __ldg(prow + 512 + u);
        pxo = __ldg(prow + 768 + u);
    }

    uint32_t ph0 = 0, ph1 = 0;
    for (int step = 0; step < SLEN; step++) {
        int p = step & 1;
        int s = dir ? (SLEN - 1 - step) : step;

        float npxi = 0.f, npxf = 0.f, npxg = 0.f, npxo = 0.f;
        if (tid < 32 && step + 1 < SLEN) {
            int sn = dir ? (SLEN - 2 - step) : (step + 1);
            const float* prow = px + (size_t)sn * 1024;
            npxi = __ldg(prow + u);
            npxf = __ldg(prow + 256 + u);
            npxg = __ldg(prow + 512 + u);
            npxo = __ldg(prow + 768 + u);
        }

        if (step > 0) {
            wait_mbar(mbar_sa + (p << 3), p ? ph1 : ph0);
            if (p) ph1 ^= 1; else ph0 ^= 1;
        }

        const double2* h2 = (const double2*)(hbuf + p * HP + q * 68);
        uint64_t a0 = 0ull, a1 = 0ull, a2 = 0ull, a3 = 0ull;
#pragma unroll
        for (int j = 0; j < 16; j += 2) {
            double2 v0 = h2[j], v1 = h2[j + 1];
            uint64_t p0 = __double_as_longlong(v0.x);
            uint64_t p1 = __double_as_longlong(v0.y);
            uint64_t p2 = __double_as_longlong(v1.x);
            uint64_t p3 = __double_as_longlong(v1.y);
            asm("fma.rn.f32x2 %0, %1, %2, %0;" : "+l"(a0) : "l"(wreg[2 * j]),     "l"(p0));
            asm("fma.rn.f32x2 %0, %1, %2, %0;" : "+l"(a1) : "l"(wreg[2 * j + 1]), "l"(p1));
            asm("fma.rn.f32x2 %0, %1, %2, %0;" : "+l"(a2) : "l"(wreg[2 * j + 2]), "l"(p2));
            asm("fma.rn.f32x2 %0, %1, %2, %0;" : "+l"(a3) : "l"(wreg[2 * j + 3]), "l"(p3));
        }
        float l0, h0f, l1, h1f, l2, h2f, l3, h3f;
        asm("mov.b64 {%0,%1}, %2;" : "=f"(l0), "=f"(h0f) : "l"(a0));
        asm("mov.b64 {%0,%1}, %2;" : "=f"(l1), "=f"(h1f) : "l"(a1));
        asm("mov.b64 {%0,%1}, %2;" : "=f"(l2), "=f"(h2f) : "l"(a2));
        asm("mov.b64 {%0,%1}, %2;" : "=f"(l3), "=f"(h3f) : "l"(a3));
        red[p][tid] = ((l0 + h0f) + (l1 + h1f)) + ((l2 + h2f) + (l3 + h3f));
        __syncthreads();

        if (tid < 32) {
            const float* r = red[p];
            int j = tid & 15;
            float di = (r[j]      + r[64 + j])  + (r[128 + j] + r[192 + j]);
            float df = (r[16 + j] + r[80 + j])  + (r[144 + j] + r[208 + j]);
            float dg = (r[32 + j] + r[96 + j])  + (r[160 + j] + r[224 + j]);
            float dz = (r[48 + j] + r[112 + j]) + (r[176 + j] + r[240 + j]);
            float ig = fast_sigmoid(pxi + di);
            float fg = fast_sigmoid(pxf + df);
            float gg = fast_tanh(pxg + dg);
            float og = fast_sigmoid(pxo + dz);
            c_reg = fg * c_reg + ig * gg;
            float hnew = og * fast_tanh(c_reg);

            if (step + 1 < SLEN) {
                int wb = p ^ 1;
#pragma unroll
                for (int rr = 0; rr < 8; rr++) {
                    uint32_t ra = wb ? rstore1[rr] : rstore0[rr];
                    asm volatile("st.shared::cluster.f32 [%0], %1;"
                                 :: "r"(ra), "f"(hnew) : "memory");
                }
                __syncwarp();
                if (tid < 16) {
                    uint32_t rm = wb ? rmb1 : rmb0;
                    asm volatile("mbarrier.arrive.release.cluster.shared::cluster.b64 _, [%0];"
                                 :: "r"(rm) : "memory");
                }
            }
            if (tid < 16) hout[s * HDIM + u] = hnew;
        }
        pxi = npxi; pxf = npxf; pxg = npxg; pxo = npxo;
    }
    asm volatile("barrier.cluster.arrive.aligned;" ::: "memory");
    asm volatile("barrier.cluster.wait.aligned;" ::: "memory");
    if (tid == 0) {
        asm volatile("mbarrier.inval.shared.b64 [%0];" :: "r"(mbar_sa) : "memory");
        asm volatile("mbarrier.inval.shared.b64 [%0];" :: "r"(mbar_sa + 8) : "memory");
    }
}

// ---------------- K3: feats ----------------
#define FEATS_SMEM ((512 * 33 + 8 * 512) * 4)
__global__ __launch_bounds__(256) void feats_kernel(const float* __restrict__ w_tag,
                                                    const float* __restrict__ b_tag)
{
    extern __shared__ float fs[];
    float* wt = fs;
    float* hs = fs + 512 * 33;

    int tid = threadIdx.x;
    for (int idx = tid; idx < NTAG * 512; idx += 256) {
        int t = idx >> 9;
        int k = idx & 511;
        wt[k * 33 + t] = w_tag[idx];
    }
    __syncthreads();

    int warp = tid >> 5, lane = tid & 31;
    float bias = b_tag[lane];
    float* hrow = hs + warp * 512;

#pragma unroll
    for (int p = 0; p < 4; p++) {
        int s = blockIdx.x * 32 + p * 8 + warp;
        float4* dsth = (float4*)hrow;
        const float4* hf4 = (const float4*)(g_h[0] + s * HDIM);
        const float4* hb4 = (const float4*)(g_h[1] + s * HDIM);
        dsth[lane] = hf4[lane];
        dsth[32 + lane] = hf4[32 + lane];
        dsth[64 + lane] = hb4[lane];
        dsth[96 + lane] = hb4[32 + lane];
        __syncwarp();
        float a0 = 0.f, a1 = 0.f, a2 = 0.f, a3 = 0.f;
#pragma unroll 8
        for (int k = 0; k < 512; k += 4) {
            float4 h = *(const float4*)(hrow + k);
            a0 += wt[(k + 0) * 33 + lane] * h.x;
            a1 += wt[(k + 1) * 33 + lane] * h.y;
            a2 += wt[(k + 2) * 33 + lane] * h.z;
            a3 += wt[(k + 3) * 33 + lane] * h.w;
        }
        g_feats[s * NTAG + lane] = (a0 + a1) + (a2 + a3) + bias;
        __syncwarp();
    }
}

// ---------------- K4a: Viterbi forward — LDS broadcast, no shfl -------------
// fv kept in double-buffered smem; each lane reads all 32 via 8 broadcast
// LDS.128 (rt~2 vs shfl rt~8), exact fmaxf tree (order-invariant == jnp.max).
// One __syncwarp per iter (write goes to the other buffer).
__global__ void __launch_bounds__(32) vit_fwd_kernel(const float* __restrict__ trans,
                                                     float* __restrict__ out,
                                                     int out_size)
{
    __shared__ __align__(16) float fvs[2][32];
    int n = threadIdx.x;
    float tr[NTAG];
#pragma unroll
    for (int p = 0; p < NTAG; p++) tr[p] = trans[n * NTAG + p];

    float fv = (n == START_TAG) ? 0.f : NEGV;
    fvs[0][n] = fv;
    __syncwarp();
    float f0 = g_feats[n];
    float f1 = g_feats[NTAG + n];
    for (int t = 0; t < SLEN; t++) {
        int pb = t & 1;
        float f2 = (t + 2 < SLEN) ? g_feats[(t + 2) * NTAG + n] : 0.f;
        g_fv[t * NTAG + n] = fv;        // entry value for step t (own reg)

        float v[NTAG];
        const float4* s4 = (const float4*)fvs[pb];
#pragma unroll
        for (int i = 0; i < 8; i++) {
            float4 x = s4[i];           // broadcast LDS.128
            v[4 * i + 0] = x.x + tr[4 * i + 0];
            v[4 * i + 1] = x.y + tr[4 * i + 1];
            v[4 * i + 2] = x.z + tr[4 * i + 2];
            v[4 * i + 3] = x.w + tr[4 * i + 3];
        }
#pragma unroll
        for (int st = 16; st > 0; st >>= 1)
#pragma unroll
            for (int q2 = 0; q2 < 16; q2++)
                if (q2 < st) v[q2] = fmaxf(v[q2], v[q2 + st]);
        fv = v[0] + f0;
        fvs[pb ^ 1][n] = fv;
        __syncwarp();
        f0 = f1; f1 = f2;
    }
    float term = fv + trans[STOP_TAG * NTAG + n];
    float bvv = term;
    int bii = n;
#pragma unroll
    for (int off = 16; off > 0; off >>= 1) {
        float ov = __shfl_down_sync(0xffffffffu, bvv, off);
        int oi = __shfl_down_sync(0xffffffffu, bii, off);
        if (ov > bvv || (ov == bvv && oi < bii)) { bvv = ov; bii = oi; }
    }
    if (n == 0) {
        if (out_size > 0) out[0] = bvv;
        g_last = bii;
    }
}

// ---------------- K4b: backpointers — PARALLEL over t ------------------------
__global__ __launch_bounds__(256) void vit_bp_kernel(const float* __restrict__ trans)
{
    __shared__ float trs[NTAG * NTAG];
    int tid = threadIdx.x;
#pragma unroll
    for (int i = tid; i < NTAG * NTAG; i += 256) trs[i] = trans[i];
    __syncthreads();

    int warp = tid >> 5, n = tid & 31;
    int t = blockIdx.x * 8 + warp;

    float fvv = g_fv[t * NTAG + n];
    float v[NTAG];
#pragma unroll
    for (int p = 0; p < NTAG; p++)
        v[p] = __shfl_sync(0xffffffffu, fvv, p) + trs[n * NTAG + p];
    float bv[16]; int bi[16];
#pragma unroll
    for (int q2 = 0; q2 < 16; q2++) {
        bool take = v[q2 + 16] > v[q2];
        bv[q2] = take ? v[q2 + 16] : v[q2];
        bi[q2] = take ? q2 + 16 : q2;
    }
#pragma unroll
    for (int st = 8; st > 0; st >>= 1) {
#pragma unroll
        for (int q2 = 0; q2 < 16; q2++) {
            if (q2 < st) {
                bool take = (bv[q2 + st] > bv[q2]) ||
                            (bv[q2 + st] == bv[q2] && bi[q2 + st] < bi[q2]);
                bv[q2] = take ? bv[q2 + st] : bv[q2];
                bi[q2] = take ? bi[q2 + st] : bi[q2];
            }
        }
    }
    g_bp[t * NTAG + n] = (unsigned char)bi[0];
}

// ---------------- K4c: backtrace (bp staged in smem) -------------------------
__global__ void __launch_bounds__(256) vit_trace_kernel(float* __restrict__ out,
                                                        int out_size)
{
    extern __shared__ unsigned char bps[];   // 64 KB
    int tid = threadIdx.x;
    const uint4* src = (const uint4*)g_bp;
    uint4* dst = (uint4*)bps;
#pragma unroll
    for (int i = 0; i < 16; i++) dst[tid + i * 256] = src[tid + i * 256];
    __syncthreads();
    if (tid == 0) {
        int tag = g_last;
        if (out_size > SLEN) out[SLEN] = (float)tag;
        for (int t = SLEN - 2; t >= 0; t--) {
            tag = bps[(t + 1) * NTAG + tag];
            if (1 + t < out_size) out[1 + t] = (float)tag;
        }
    }
}

// ---------------- launch -----------------------------------------------------
extern "C" void kernel_launch(void* const* d_in, const int* in_sizes, int n_in,
                              void* d_out, int out_size)
{
    const int*   sent   = (const int*)d_in[0];
    const float* embed  = (const float*)d_in[1];
    const float* w_ih_f = (const float*)d_in[2];
    const float* w_hh_f = (const float*)d_in[3];
    const float* b_f    = (const float*)d_in[4];
    const float* w_ih_b = (const float*)d_in[5];
    const float* w_hh_b = (const float*)d_in[6];
    const float* b_b    = (const float*)d_in[7];
    const float* w_tag  = (const float*)d_in[8];
    const float* b_tag  = (const float*)d_in[9];
    const float* trans  = (const float*)d_in[10];
    const float* h0     = (const float*)d_in[11];
    const float* c0     = (const float*)d_in[12];
    float* out = (float*)d_out;

    cudaFuncSetAttribute(lstm_kernel,
                         cudaFuncAttributeNonPortableClusterSizeAllowed, 1);
    cudaFuncSetAttribute(feats_kernel,
                         cudaFuncAttributeMaxDynamicSharedMemorySize, FEATS_SMEM);
    cudaFuncSetAttribute(vit_trace_kernel,
                         cudaFuncAttributeMaxDynamicSharedMemorySize, SLEN * NTAG);

    dim3 gg(SLEN / BM, (4 * HDIM) / BN, 2);
    px_gemm_kernel<<<gg, 256>>>(sent, embed, w_ih_f, b_f, w_ih_b, b_b);

    lstm_kernel<<<2 * CL, 256>>>(w_hh_f, w_hh_b, h0, c0);

    feats_kernel<<<SLEN / 32, 256, FEATS_SMEM>>>(w_tag, b_tag);

    vit_fwd_kernel<<<1, 32>>>(trans, out, out_size);
    vit_bp_kernel<<<SLEN / 8, 256>>>(trans);
    vit_trace_kernel<<<1, 256, SLEN * NTAG>>>(out, out_size);
}

// round 14
// speedup vs baseline: 1.0994x; 1.0994x over previous
#include <cuda_runtime.h>
#include <cstdint>

#define SLEN 2048
#define EDIM 512
#define HDIM 256
#define NTAG 32
#define START_TAG 30
#define STOP_TAG 31
#define NEGV (-10000.0f)
#define HP 272   // padded per-buffer h stride: 4 chunks x (64+4) floats
#define CL 16    // cluster size (CTAs per direction)

// ---------------- scratch (device globals; no runtime alloc) ----------------
__device__ float g_px[2][SLEN * 4 * HDIM];
__device__ float g_h[2][SLEN * HDIM];
__device__ float g_feats[SLEN * NTAG];
__device__ float g_fv[SLEN * NTAG];            // fv at ENTRY of step t
__device__ unsigned char g_bp[SLEN * NTAG];    // backpointers
__device__ int g_last;                         // terminal argmax

// ---------------- K1: px = embed[sent] @ W_ih^T + b (gather fused) ----------
#define BM 128
#define BN 128
#define BK 16
#define SPAD 132

__global__ __launch_bounds__(256) void px_gemm_kernel(
    const int* __restrict__ sent, const float* __restrict__ embed,
    const float* __restrict__ w_f, const float* __restrict__ b_f,
    const float* __restrict__ w_b, const float* __restrict__ b_b)
{
    int dir = blockIdx.z;
    const float* W = dir ? w_b : w_f;
    const float* bias = dir ? b_b : b_f;
    float* C = g_px[dir];

    __shared__ float As[BK * SPAD];
    __shared__ float Bs[BK * SPAD];
    __shared__ int sidx[BM];

    int tid = threadIdx.x;
    int m_block = blockIdx.x * BM;
    int n_block = blockIdx.y * BN;

    if (tid < BM) sidx[tid] = sent[m_block + tid];

    int lm = tid >> 2;
    int lk4 = (tid & 3) * 4;
    int ty = tid >> 4;
    int tx = tid & 15;
    int m0 = ty * 8, n0 = tx * 8;

    __syncthreads();
    int arow0 = sidx[lm];
    int arow1 = sidx[lm + 64];

    float acc[8][8];
#pragma unroll
    for (int i = 0; i < 8; i++)
#pragma unroll
        for (int j = 0; j < 8; j++) acc[i][j] = 0.f;

    for (int kt = 0; kt < EDIM; kt += BK) {
#pragma unroll
        for (int h = 0; h < 2; h++) {
            int m = lm + h * 64;
            int arow = h ? arow1 : arow0;
            float4 a = *(const float4*)(embed + (size_t)arow * EDIM + kt + lk4);
            As[(lk4 + 0) * SPAD + m] = a.x;
            As[(lk4 + 1) * SPAD + m] = a.y;
            As[(lk4 + 2) * SPAD + m] = a.z;
            As[(lk4 + 3) * SPAD + m] = a.w;
            float4 b = *(const float4*)(W + (size_t)(n_block + m) * EDIM + kt + lk4);
            Bs[(lk4 + 0) * SPAD + m] = b.x;
            Bs[(lk4 + 1) * SPAD + m] = b.y;
            Bs[(lk4 + 2) * SPAD + m] = b.z;
            Bs[(lk4 + 3) * SPAD + m] = b.w;
        }
        __syncthreads();
#pragma unroll
        for (int k = 0; k < BK; k++) {
            float ar[8], br[8];
            *(float4*)(ar + 0) = *(const float4*)(&As[k * SPAD + m0 + 0]);
            *(float4*)(ar + 4) = *(const float4*)(&As[k * SPAD + m0 + 4]);
            *(float4*)(br + 0) = *(const float4*)(&Bs[k * SPAD + n0 + 0]);
            *(float4*)(br + 4) = *(const float4*)(&Bs[k * SPAD + n0 + 4]);
#pragma unroll
            for (int i = 0; i < 8; i++)
#pragma unroll
                for (int j = 0; j < 8; j++) acc[i][j] += ar[i] * br[j];
        }
        __syncthreads();
    }
#pragma unroll
    for (int i = 0; i < 8; i++) {
        int row = m_block + m0 + i;
#pragma unroll
        for (int j4 = 0; j4 < 8; j4 += 4) {
            int n = n_block + n0 + j4;
            float4 v;
            v.x = acc[i][j4 + 0] + bias[n + 0];
            v.y = acc[i][j4 + 1] + bias[n + 1];
            v.z = acc[i][j4 + 2] + bias[n + 2];
            v.w = acc[i][j4 + 3] + bias[n + 3];
            *(float4*)(C + row * (4 * HDIM) + n) = v;
        }
    }
}

// ---------------- K2: recurrent LSTM — 16-CTA cluster per direction ---------
// (unchanged — best known)
__device__ __forceinline__ float fast_sigmoid(float x) {
    return __fdividef(1.f, 1.f + __expf(-x));
}
__device__ __forceinline__ float fast_tanh(float x) {
    return 1.f - __fdividef(2.f, __expf(2.f * x) + 1.f);
}
__device__ __forceinline__ void wait_mbar(uint32_t addr, uint32_t parity) {
    uint32_t done;
    asm volatile(
        "{\n .reg .pred P;\n"
        " mbarrier.try_wait.parity.acquire.cluster.shared::cta.b64 P, [%1], %2;\n"
        " selp.b32 %0, 1, 0, P;\n}"
        : "=r"(done) : "r"(addr), "r"(parity) : "memory");
    while (!done) {
        asm volatile(
            "{\n .reg .pred P;\n"
            " mbarrier.try_wait.parity.acquire.cluster.shared::cta.b64 P, [%1], %2, 0x989680;\n"
            " selp.b32 %0, 1, 0, P;\n}"
            : "=r"(done) : "r"(addr), "r"(parity) : "memory");
    }
}

__global__ void __cluster_dims__(CL, 1, 1) __launch_bounds__(256, 1) lstm_kernel(
    const float* __restrict__ w_hh_f, const float* __restrict__ w_hh_b,
    const float* __restrict__ h0, const float* __restrict__ c0)
{
    __shared__ __align__(16) float hbuf[2 * HP];
    __shared__ __align__(16) float red[2][256];
    __shared__ __align__(8) unsigned long long mbars[2];

    int tid = threadIdx.x;
    int dir = blockIdx.x >> 4;
    uint32_t crank;
    asm("mov.u32 %0, %%cluster_ctarank;" : "=r"(crank));
    int base_u = crank * 16;

    const float* Whh = dir ? w_hh_b : w_hh_f;
    const float* px = g_px[dir];
    float* hout = g_h[dir];

    int q = tid >> 6;
    int lr = tid & 63;
    int gr = ((lr >> 4) << 8) + base_u + (lr & 15);

    uint64_t wreg[32];
    {
        const uint64_t* ws = (const uint64_t*)(Whh + (size_t)gr * 256 + q * 64);
#pragma unroll
        for (int j = 0; j < 32; j++) wreg[j] = ws[j];
    }

    hbuf[tid + (tid >> 6) * 4] = h0[dir * HDIM + tid];
    int u = base_u + (tid & 15);
    float c_reg = (tid < 32) ? c0[dir * HDIM + u] : 0.f;

    uint32_t hbuf_sa = (uint32_t)__cvta_generic_to_shared(hbuf);
    uint32_t mbar_sa = (uint32_t)__cvta_generic_to_shared(mbars);

    if (tid == 0) {
        asm volatile("mbarrier.init.shared.b64 [%0], 16;" :: "r"(mbar_sa) : "memory");
        asm volatile("mbarrier.init.shared.b64 [%0], 16;" :: "r"(mbar_sa + 8) : "memory");
        asm volatile("fence.mbarrier_init.release.cluster;" ::: "memory");
    }

    uint32_t rstore0[8], rstore1[8];
    uint32_t rmb0 = 0, rmb1 = 0;
    if (tid < 32) {
        int slot = u + (u >> 6) * 4;
        uint32_t d0 = hbuf_sa + ((0 * HP + slot) << 2);
        uint32_t d1 = hbuf_sa + ((1 * HP + slot) << 2);
        int rbase = (tid >> 4) * 8;
#pragma unroll
        for (int rr = 0; rr < 8; rr++) {
            asm("mapa.shared::cluster.u32 %0, %1, %2;" : "=r"(rstore0[rr]) : "r"(d0), "r"(rbase + rr));
            asm("mapa.shared::cluster.u32 %0, %1, %2;" : "=r"(rstore1[rr]) : "r"(d1), "r"(rbase + rr));
        }
        if (tid < 16) {
            asm("mapa.shared::cluster.u32 %0, %1, %2;" : "=r"(rmb0) : "r"(mbar_sa), "r"(tid));
            asm("mapa.shared::cluster.u32 %0, %1, %2;" : "=r"(rmb1) : "r"(mbar_sa + 8), "r"(tid));
        }
    }

    __syncthreads();
    asm volatile("barrier.cluster.arrive.aligned;" ::: "memory");
    asm volatile("barrier.cluster.wait.aligned;" ::: "memory");

    float pxi = 0.f, pxf = 0.f, pxg = 0.f, pxo = 0.f;
    if (tid < 32) {
        const float* prow = px + (size_t)(dir ? SLEN - 1 : 0) * 1024;
        pxi = __ldg(prow + u);
        pxf = __ldg(prow + 256 + u);
        pxg = __ldg(prow + 512 + u);
        pxo = __ldg(prow + 768 + u);
    }

    uint32_t ph0 = 0, ph1 = 0;
    for (int step = 0; step < SLEN; step++) {
        int p = step & 1;
        int s = dir ? (SLEN - 1 - step) : step;

        float npxi = 0.f, npxf = 0.f, npxg = 0.f, npxo = 0.f;
        if (tid < 32 && step + 1 < SLEN) {
            int sn = dir ? (SLEN - 2 - step) : (step + 1);
            const float* prow = px + (size_t)sn * 1024;
            npxi = __ldg(prow + u);
            npxf = __ldg(prow + 256 + u);
            npxg = __ldg(prow + 512 + u);
            npxo = __ldg(prow + 768 + u);
        }

        if (step > 0) {
            wait_mbar(mbar_sa + (p << 3), p ? ph1 : ph0);
            if (p) ph1 ^= 1; else ph0 ^= 1;
        }

        const double2* h2 = (const double2*)(hbuf + p * HP + q * 68);
        uint64_t a0 = 0ull, a1 = 0ull, a2 = 0ull, a3 = 0ull;
#pragma unroll
        for (int j = 0; j < 16; j += 2) {
            double2 v0 = h2[j], v1 = h2[j + 1];
            uint64_t p0 = __double_as_longlong(v0.x);
            uint64_t p1 = __double_as_longlong(v0.y);
            uint64_t p2 = __double_as_longlong(v1.x);
            uint64_t p3 = __double_as_longlong(v1.y);
            asm("fma.rn.f32x2 %0, %1, %2, %0;" : "+l"(a0) : "l"(wreg[2 * j]),     "l"(p0));
            asm("fma.rn.f32x2 %0, %1, %2, %0;" : "+l"(a1) : "l"(wreg[2 * j + 1]), "l"(p1));
            asm("fma.rn.f32x2 %0, %1, %2, %0;" : "+l"(a2) : "l"(wreg[2 * j + 2]), "l"(p2));
            asm("fma.rn.f32x2 %0, %1, %2, %0;" : "+l"(a3) : "l"(wreg[2 * j + 3]), "l"(p3));
        }
        float l0, h0f, l1, h1f, l2, h2f, l3, h3f;
        asm("mov.b64 {%0,%1}, %2;" : "=f"(l0), "=f"(h0f) : "l"(a0));
        asm("mov.b64 {%0,%1}, %2;" : "=f"(l1), "=f"(h1f) : "l"(a1));
        asm("mov.b64 {%0,%1}, %2;" : "=f"(l2), "=f"(h2f) : "l"(a2));
        asm("mov.b64 {%0,%1}, %2;" : "=f"(l3), "=f"(h3f) : "l"(a3));
        red[p][tid] = ((l0 + h0f) + (l1 + h1f)) + ((l2 + h2f) + (l3 + h3f));
        __syncthreads();

        if (tid < 32) {
            const float* r = red[p];
            int j = tid & 15;
            float di = (r[j]      + r[64 + j])  + (r[128 + j] + r[192 + j]);
            float df = (r[16 + j] + r[80 + j])  + (r[144 + j] + r[208 + j]);
            float dg = (r[32 + j] + r[96 + j])  + (r[160 + j] + r[224 + j]);
            float dz = (r[48 + j] + r[112 + j]) + (r[176 + j] + r[240 + j]);
            float ig = fast_sigmoid(pxi + di);
            float fg = fast_sigmoid(pxf + df);
            float gg = fast_tanh(pxg + dg);
            float og = fast_sigmoid(pxo + dz);
            c_reg = fg * c_reg + ig * gg;
            float hnew = og * fast_tanh(c_reg);

            if (step + 1 < SLEN) {
                int wb = p ^ 1;
#pragma unroll
                for (int rr = 0; rr < 8; rr++) {
                    uint32_t ra = wb ? rstore1[rr] : rstore0[rr];
                    asm volatile("st.shared::cluster.f32 [%0], %1;"
                                 :: "r"(ra), "f"(hnew) : "memory");
                }
                __syncwarp();
                if (tid < 16) {
                    uint32_t rm = wb ? rmb1 : rmb0;
                    asm volatile("mbarrier.arrive.release.cluster.shared::cluster.b64 _, [%0];"
                                 :: "r"(rm) : "memory");
                }
            }
            if (tid < 16) hout[s * HDIM + u] = hnew;
        }
        pxi = npxi; pxf = npxf; pxg = npxg; pxo = npxo;
    }
    asm volatile("barrier.cluster.arrive.aligned;" ::: "memory");
    asm volatile("barrier.cluster.wait.aligned;" ::: "memory");
    if (tid == 0) {
        asm volatile("mbarrier.inval.shared.b64 [%0];" :: "r"(mbar_sa) : "memory");
        asm volatile("mbarrier.inval.shared.b64 [%0];" :: "r"(mbar_sa + 8) : "memory");
    }
}

// ---------------- K3: feats ----------------
#define FEATS_SMEM ((512 * 33 + 8 * 512) * 4)
__global__ __launch_bounds__(256) void feats_kernel(const float* __restrict__ w_tag,
                                                    const float* __restrict__ b_tag)
{
    extern __shared__ float fs[];
    float* wt = fs;
    float* hs = fs + 512 * 33;

    int tid = threadIdx.x;
    for (int idx = tid; idx < NTAG * 512; idx += 256) {
        int t = idx >> 9;
        int k = idx & 511;
        wt[k * 33 + t] = w_tag[idx];
    }
    __syncthreads();

    int warp = tid >> 5, lane = tid & 31;
    float bias = b_tag[lane];
    float* hrow = hs + warp * 512;

#pragma unroll
    for (int p = 0; p < 4; p++) {
        int s = blockIdx.x * 32 + p * 8 + warp;
        float4* dsth = (float4*)hrow;
        const float4* hf4 = (const float4*)(g_h[0] + s * HDIM);
        const float4* hb4 = (const float4*)(g_h[1] + s * HDIM);
        dsth[lane] = hf4[lane];
        dsth[32 + lane] = hf4[32 + lane];
        dsth[64 + lane] = hb4[lane];
        dsth[96 + lane] = hb4[32 + lane];
        __syncwarp();
        float a0 = 0.f, a1 = 0.f, a2 = 0.f, a3 = 0.f;
#pragma unroll 8
        for (int k = 0; k < 512; k += 4) {
            float4 h = *(const float4*)(hrow + k);
            a0 += wt[(k + 0) * 33 + lane] * h.x;
            a1 += wt[(k + 1) * 33 + lane] * h.y;
            a2 += wt[(k + 2) * 33 + lane] * h.z;
            a3 += wt[(k + 3) * 33 + lane] * h.w;
        }
        g_feats[s * NTAG + lane] = (a0 + a1) + (a2 + a3) + bias;
        __syncwarp();
    }
}

// ---------------- K4a: Viterbi forward — 4 warps (one per SMSP) -------------
// Thread (n=tid>>2, c=tid&3) owns an 8-wide chunk of tag n's row.
// Phase 1: 8 adds + 7-fmaxf tree -> partial max -> STS part[tid]; bar.
// Phase 2: LDS.128 of 4 partials + 3 fmaxf + feat add (exact: identical
// elementwise adds; max order-invariant == jnp.max) -> fv_new; bar.
// Spreads issue across 4 SMSPs (single-warp version was 1-scheduler-bound).
__global__ void __launch_bounds__(128) vit_fwd_kernel(const float* __restrict__ trans,
                                                      float* __restrict__ out,
                                                      int out_size)
{
    __shared__ __align__(16) float fvs[2][32];
    __shared__ __align__(16) float part[128];
    int tid = threadIdx.x;
    int n = tid >> 2, c = tid & 3;

    float tr[8];
#pragma unroll
    for (int j = 0; j < 8; j++) tr[j] = trans[n * NTAG + c * 8 + j];

    float fv_n = (n == START_TAG) ? 0.f : NEGV;   // entry fv for current t
    if (tid < 32) fvs[0][tid] = (tid == START_TAG) ? 0.f : NEGV;

    float f0 = g_feats[n];
    float f1 = g_feats[NTAG + n];
    __syncthreads();

    for (int t = 0; t < SLEN; t++) {
        int pb = t & 1;
        float f2 = (t + 2 < SLEN) ? g_feats[(t + 2) * NTAG + n] : 0.f;
        if (c == 0) g_fv[t * NTAG + n] = fv_n;     // entry value (off path)

        // phase 1: partial max over this 8-chunk
        const float4* s4 = (const float4*)(fvs[pb] + c * 8);
        float4 x0 = s4[0], x1 = s4[1];
        float v0 = x0.x + tr[0], v1 = x0.y + tr[1];
        float v2 = x0.z + tr[2], v3 = x0.w + tr[3];
        float v4 = x1.x + tr[4], v5 = x1.y + tr[5];
        float v6 = x1.z + tr[6], v7 = x1.w + tr[7];
        float m = fmaxf(fmaxf(fmaxf(v0, v1), fmaxf(v2, v3)),
                        fmaxf(fmaxf(v4, v5), fmaxf(v6, v7)));
        part[tid] = m;
        __syncthreads();

        // phase 2: combine 4 partials, add feat
        float4 pm = *(const float4*)(part + n * 4);
        float best = fmaxf(fmaxf(pm.x, pm.y), fmaxf(pm.z, pm.w));
        float fv_new = best + f0;
        if (c == 0) fvs[pb ^ 1][n] = fv_new;
        __syncthreads();

        fv_n = fv_new;
        f0 = f1; f1 = f2;
    }

    // terminal score + first-index argmax
    float term = fv_n + trans[STOP_TAG * NTAG + n];
    if (c == 0) part[n] = term;
    __syncthreads();
    if (tid < 32) {
        float bvv = part[tid];
        int bii = tid;
#pragma unroll
        for (int off = 16; off > 0; off >>= 1) {
            float ov = __shfl_down_sync(0xffffffffu, bvv, off);
            int oi = __shfl_down_sync(0xffffffffu, bii, off);
            if (ov > bvv || (ov == bvv && oi < bii)) { bvv = ov; bii = oi; }
        }
        if (tid == 0) {
            if (out_size > 0) out[0] = bvv;
            g_last = bii;
        }
    }
}

// ---------------- K4b: backpointers — PARALLEL over t ------------------------
__global__ __launch_bounds__(256) void vit_bp_kernel(const float* __restrict__ trans)
{
    __shared__ float trs[NTAG * NTAG];
    int tid = threadIdx.x;
#pragma unroll
    for (int i = tid; i < NTAG * NTAG; i += 256) trs[i] = trans[i];
    __syncthreads();

    int warp = tid >> 5, n = tid & 31;
    int t = blockIdx.x * 8 + warp;

    float fvv = g_fv[t * NTAG + n];
    float v[NTAG];
#pragma unroll
    for (int p = 0; p < NTAG; p++)
        v[p] = __shfl_sync(0xffffffffu, fvv, p) + trs[n * NTAG + p];
    float bv[16]; int bi[16];
#pragma unroll
    for (int q2 = 0; q2 < 16; q2++) {
        bool take = v[q2 + 16] > v[q2];
        bv[q2] = take ? v[q2 + 16] : v[q2];
        bi[q2] = take ? q2 + 16 : q2;
    }
#pragma unroll
    for (int st = 8; st > 0; st >>= 1) {
#pragma unroll
        for (int q2 = 0; q2 < 16; q2++) {
            if (q2 < st) {
                bool take = (bv[q2 + st] > bv[q2]) ||
                            (bv[q2 + st] == bv[q2] && bi[q2 + st] < bi[q2]);
                bv[q2] = take ? bv[q2 + st] : bv[q2];
                bi[q2] = take ? bi[q2 + st] : bi[q2];
            }
        }
    }
    g_bp[t * NTAG + n] = (unsigned char)bi[0];
}

// ---------------- K4c: backtrace (bp staged in smem) -------------------------
__global__ void __launch_bounds__(256) vit_trace_kernel(float* __restrict__ out,
                                                        int out_size)
{
    extern __shared__ unsigned char bps[];   // 64 KB
    int tid = threadIdx.x;
    const uint4* src = (const uint4*)g_bp;
    uint4* dst = (uint4*)bps;
#pragma unroll
    for (int i = 0; i < 16; i++) dst[tid + i * 256] = src[tid + i * 256];
    __syncthreads();
    if (tid == 0) {
        int tag = g_last;
        if (out_size > SLEN) out[SLEN] = (float)tag;
        for (int t = SLEN - 2; t >= 0; t--) {
            tag = bps[(t + 1) * NTAG + tag];
            if (1 + t < out_size) out[1 + t] = (float)tag;
        }
    }
}

// ---------------- launch -----------------------------------------------------
extern "C" void kernel_launch(void* const* d_in, const int* in_sizes, int n_in,
                              void* d_out, int out_size)
{
    const int*   sent   = (const int*)d_in[0];
    const float* embed  = (const float*)d_in[1];
    const float* w_ih_f = (const float*)d_in[2];
    const float* w_hh_f = (const float*)d_in[3];
    const float* b_f    = (const float*)d_in[4];
    const float* w_ih_b = (const float*)d_in[5];
    const float* w_hh_b = (const float*)d_in[6];
    const float* b_b    = (const float*)d_in[7];
    const float* w_tag  = (const float*)d_in[8];
    const float* b_tag  = (const float*)d_in[9];
    const float* trans  = (const float*)d_in[10];
    const float* h0     = (const float*)d_in[11];
    const float* c0     = (const float*)d_in[12];
    float* out = (float*)d_out;

    cudaFuncSetAttribute(lstm_kernel,
                         cudaFuncAttributeNonPortableClusterSizeAllowed, 1);
    cudaFuncSetAttribute(feats_kernel,
                         cudaFuncAttributeMaxDynamicSharedMemorySize, FEATS_SMEM);
    cudaFuncSetAttribute(vit_trace_kernel,
                         cudaFuncAttributeMaxDynamicSharedMemorySize, SLEN * NTAG);

    dim3 gg(SLEN / BM, (4 * HDIM) / BN, 2);
    px_gemm_kernel<<<gg, 256>>>(sent, embed, w_ih_f, b_f, w_ih_b, b_b);

    lstm_kernel<<<2 * CL, 256>>>(w_hh_f, w_hh_b, h0, c0);

    feats_kernel<<<SLEN / 32, 256, FEATS_SMEM>>>(w_tag, b_tag);

    vit_fwd_kernel<<<1, 128>>>(trans, out, out_size);
    vit_bp_kernel<<<SLEN / 8, 256>>>(trans);
    vit_trace_kernel<<<1, 256, SLEN * NTAG>>>(out, out_size);
}

// round 15
// speedup vs baseline: 1.1121x; 1.0116x over previous
#include <cuda_runtime.h>
#include <cstdint>

#define SLEN 2048
#define EDIM 512
#define HDIM 256
#define NTAG 32
#define START_TAG 30
#define STOP_TAG 31
#define NEGV (-10000.0f)
#define HP 272   // padded per-buffer h stride: 4 chunks x (64+4) floats
#define CL 16    // cluster size (CTAs per direction)

// ---------------- scratch (device globals; no runtime alloc) ----------------
__device__ float g_px[2][SLEN * 4 * HDIM];
__device__ float g_h[2][SLEN * HDIM];
__device__ float g_feats[SLEN * NTAG];
__device__ float g_fv[SLEN * NTAG];            // fv at ENTRY of step t
__device__ unsigned char g_bp[SLEN * NTAG];    // backpointers
__device__ int g_last;                         // terminal argmax

// ---------------- K1: px = embed[sent] @ W_ih^T + b (gather fused) ----------
#define BM 128
#define BN 128
#define BK 16
#define SPAD 132

__global__ __launch_bounds__(256) void px_gemm_kernel(
    const int* __restrict__ sent, const float* __restrict__ embed,
    const float* __restrict__ w_f, const float* __restrict__ b_f,
    const float* __restrict__ w_b, const float* __restrict__ b_b)
{
    int dir = blockIdx.z;
    const float* W = dir ? w_b : w_f;
    const float* bias = dir ? b_b : b_f;
    float* C = g_px[dir];

    __shared__ float As[BK * SPAD];
    __shared__ float Bs[BK * SPAD];
    __shared__ int sidx[BM];

    int tid = threadIdx.x;
    int m_block = blockIdx.x * BM;
    int n_block = blockIdx.y * BN;

    if (tid < BM) sidx[tid] = sent[m_block + tid];

    int lm = tid >> 2;
    int lk4 = (tid & 3) * 4;
    int ty = tid >> 4;
    int tx = tid & 15;
    int m0 = ty * 8, n0 = tx * 8;

    __syncthreads();
    int arow0 = sidx[lm];
    int arow1 = sidx[lm + 64];

    float acc[8][8];
#pragma unroll
    for (int i = 0; i < 8; i++)
#pragma unroll
        for (int j = 0; j < 8; j++) acc[i][j] = 0.f;

    for (int kt = 0; kt < EDIM; kt += BK) {
#pragma unroll
        for (int h = 0; h < 2; h++) {
            int m = lm + h * 64;
            int arow = h ? arow1 : arow0;
            float4 a = *(const float4*)(embed + (size_t)arow * EDIM + kt + lk4);
            As[(lk4 + 0) * SPAD + m] = a.x;
            As[(lk4 + 1) * SPAD + m] = a.y;
            As[(lk4 + 2) * SPAD + m] = a.z;
            As[(lk4 + 3) * SPAD + m] = a.w;
            float4 b = *(const float4*)(W + (size_t)(n_block + m) * EDIM + kt + lk4);
            Bs[(lk4 + 0) * SPAD + m] = b.x;
            Bs[(lk4 + 1) * SPAD + m] = b.y;
            Bs[(lk4 + 2) * SPAD + m] = b.z;
            Bs[(lk4 + 3) * SPAD + m] = b.w;
        }
        __syncthreads();
#pragma unroll
        for (int k = 0; k < BK; k++) {
            float ar[8], br[8];
            *(float4*)(ar + 0) = *(const float4*)(&As[k * SPAD + m0 + 0]);
            *(float4*)(ar + 4) = *(const float4*)(&As[k * SPAD + m0 + 4]);
            *(float4*)(br + 0) = *(const float4*)(&Bs[k * SPAD + n0 + 0]);
            *(float4*)(br + 4) = *(const float4*)(&Bs[k * SPAD + n0 + 4]);
#pragma unroll
            for (int i = 0; i < 8; i++)
#pragma unroll
                for (int j = 0; j < 8; j++) acc[i][j] += ar[i] * br[j];
        }
        __syncthreads();
    }
#pragma unroll
    for (int i = 0; i < 8; i++) {
        int row = m_block + m0 + i;
#pragma unroll
        for (int j4 = 0; j4 < 8; j4 += 4) {
            int n = n_block + n0 + j4;
            float4 v;
            v.x = acc[i][j4 + 0] + bias[n + 0];
            v.y = acc[i][j4 + 1] + bias[n + 1];
            v.z = acc[i][j4 + 2] + bias[n + 2];
            v.w = acc[i][j4 + 3] + bias[n + 3];
            *(float4*)(C + row * (4 * HDIM) + n) = v;
        }
    }
}

// ---------------- K2: recurrent LSTM — 16-CTA cluster per direction ---------
// (unchanged — best known)
__device__ __forceinline__ float fast_sigmoid(float x) {
    return __fdividef(1.f, 1.f + __expf(-x));
}
__device__ __forceinline__ float fast_tanh(float x) {
    return 1.f - __fdividef(2.f, __expf(2.f * x) + 1.f);
}
__device__ __forceinline__ void wait_mbar(uint32_t addr, uint32_t parity) {
    uint32_t done;
    asm volatile(
        "{\n .reg .pred P;\n"
        " mbarrier.try_wait.parity.acquire.cluster.shared::cta.b64 P, [%1], %2;\n"
        " selp.b32 %0, 1, 0, P;\n}"
        : "=r"(done) : "r"(addr), "r"(parity) : "memory");
    while (!done) {
        asm volatile(
            "{\n .reg .pred P;\n"
            " mbarrier.try_wait.parity.acquire.cluster.shared::cta.b64 P, [%1], %2, 0x989680;\n"
            " selp.b32 %0, 1, 0, P;\n}"
            : "=r"(done) : "r"(addr), "r"(parity) : "memory");
    }
}

__global__ void __cluster_dims__(CL, 1, 1) __launch_bounds__(256, 1) lstm_kernel(
    const float* __restrict__ w_hh_f, const float* __restrict__ w_hh_b,
    const float* __restrict__ h0, const float* __restrict__ c0)
{
    __shared__ __align__(16) float hbuf[2 * HP];
    __shared__ __align__(16) float red[2][256];
    __shared__ __align__(8) unsigned long long mbars[2];

    int tid = threadIdx.x;
    int dir = blockIdx.x >> 4;
    uint32_t crank;
    asm("mov.u32 %0, %%cluster_ctarank;" : "=r"(crank));
    int base_u = crank * 16;

    const float* Whh = dir ? w_hh_b : w_hh_f;
    const float* px = g_px[dir];
    float* hout = g_h[dir];

    int q = tid >> 6;
    int lr = tid & 63;
    int gr = ((lr >> 4) << 8) + base_u + (lr & 15);

    uint64_t wreg[32];
    {
        const uint64_t* ws = (const uint64_t*)(Whh + (size_t)gr * 256 + q * 64);
#pragma unroll
        for (int j = 0; j < 32; j++) wreg[j] = ws[j];
    }

    hbuf[tid + (tid >> 6) * 4] = h0[dir * HDIM + tid];
    int u = base_u + (tid & 15);
    float c_reg = (tid < 32) ? c0[dir * HDIM + u] : 0.f;

    uint32_t hbuf_sa = (uint32_t)__cvta_generic_to_shared(hbuf);
    uint32_t mbar_sa = (uint32_t)__cvta_generic_to_shared(mbars);

    if (tid == 0) {
        asm volatile("mbarrier.init.shared.b64 [%0], 16;" :: "r"(mbar_sa) : "memory");
        asm volatile("mbarrier.init.shared.b64 [%0], 16;" :: "r"(mbar_sa + 8) : "memory");
        asm volatile("fence.mbarrier_init.release.cluster;" ::: "memory");
    }

    uint32_t rstore0[8], rstore1[8];
    uint32_t rmb0 = 0, rmb1 = 0;
    if (tid < 32) {
        int slot = u + (u >> 6) * 4;
        uint32_t d0 = hbuf_sa + ((0 * HP + slot) << 2);
        uint32_t d1 = hbuf_sa + ((1 * HP + slot) << 2);
        int rbase = (tid >> 4) * 8;
#pragma unroll
        for (int rr = 0; rr < 8; rr++) {
            asm("mapa.shared::cluster.u32 %0, %1, %2;" : "=r"(rstore0[rr]) : "r"(d0), "r"(rbase + rr));
            asm("mapa.shared::cluster.u32 %0, %1, %2;" : "=r"(rstore1[rr]) : "r"(d1), "r"(rbase + rr));
        }
        if (tid < 16) {
            asm("mapa.shared::cluster.u32 %0, %1, %2;" : "=r"(rmb0) : "r"(mbar_sa), "r"(tid));
            asm("mapa.shared::cluster.u32 %0, %1, %2;" : "=r"(rmb1) : "r"(mbar_sa + 8), "r"(tid));
        }
    }

    __syncthreads();
    asm volatile("barrier.cluster.arrive.aligned;" ::: "memory");
    asm volatile("barrier.cluster.wait.aligned;" ::: "memory");

    float pxi = 0.f, pxf = 0.f, pxg = 0.f, pxo = 0.f;
    if (tid < 32) {
        const float* prow = px + (size_t)(dir ? SLEN - 1 : 0) * 1024;
        pxi = __ldg(prow + u);
        pxf = __ldg(prow + 256 + u);
        pxg = __ldg(prow + 512 + u);
        pxo = __ldg(prow + 768 + u);
    }

    uint32_t ph0 = 0, ph1 = 0;
    for (int step = 0; step < SLEN; step++) {
        int p = step & 1;
        int s = dir ? (SLEN - 1 - step) : step;

        float npxi = 0.f, npxf = 0.f, npxg = 0.f, npxo = 0.f;
        if (tid < 32 && step + 1 < SLEN) {
            int sn = dir ? (SLEN - 2 - step) : (step + 1);
            const float* prow = px + (size_t)sn * 1024;
            npxi = __ldg(prow + u);
            npxf = __ldg(prow + 256 + u);
            npxg = __ldg(prow + 512 + u);
            npxo = __ldg(prow + 768 + u);
        }

        if (step > 0) {
            wait_mbar(mbar_sa + (p << 3), p ? ph1 : ph0);
            if (p) ph1 ^= 1; else ph0 ^= 1;
        }

        const double2* h2 = (const double2*)(hbuf + p * HP + q * 68);
        uint64_t a0 = 0ull, a1 = 0ull, a2 = 0ull, a3 = 0ull;
#pragma unroll
        for (int j = 0; j < 16; j += 2) {
            double2 v0 = h2[j], v1 = h2[j + 1];
            uint64_t p0 = __double_as_longlong(v0.x);
            uint64_t p1 = __double_as_longlong(v0.y);
            uint64_t p2 = __double_as_longlong(v1.x);
            uint64_t p3 = __double_as_longlong(v1.y);
            asm("fma.rn.f32x2 %0, %1, %2, %0;" : "+l"(a0) : "l"(wreg[2 * j]),     "l"(p0));
            asm("fma.rn.f32x2 %0, %1, %2, %0;" : "+l"(a1) : "l"(wreg[2 * j + 1]), "l"(p1));
            asm("fma.rn.f32x2 %0, %1, %2, %0;" : "+l"(a2) : "l"(wreg[2 * j + 2]), "l"(p2));
            asm("fma.rn.f32x2 %0, %1, %2, %0;" : "+l"(a3) : "l"(wreg[2 * j + 3]), "l"(p3));
        }
        float l0, h0f, l1, h1f, l2, h2f, l3, h3f;
        asm("mov.b64 {%0,%1}, %2;" : "=f"(l0), "=f"(h0f) : "l"(a0));
        asm("mov.b64 {%0,%1}, %2;" : "=f"(l1), "=f"(h1f) : "l"(a1));
        asm("mov.b64 {%0,%1}, %2;" : "=f"(l2), "=f"(h2f) : "l"(a2));
        asm("mov.b64 {%0,%1}, %2;" : "=f"(l3), "=f"(h3f) : "l"(a3));
        red[p][tid] = ((l0 + h0f) + (l1 + h1f)) + ((l2 + h2f) + (l3 + h3f));
        __syncthreads();

        if (tid < 32) {
            const float* r = red[p];
            int j = tid & 15;
            float di = (r[j]      + r[64 + j])  + (r[128 + j] + r[192 + j]);
            float df = (r[16 + j] + r[80 + j])  + (r[144 + j] + r[208 + j]);
            float dg = (r[32 + j] + r[96 + j])  + (r[160 + j] + r[224 + j]);
            float dz = (r[48 + j] + r[112 + j]) + (r[176 + j] + r[240 + j]);
            float ig = fast_sigmoid(pxi + di);
            float fg = fast_sigmoid(pxf + df);
            float gg = fast_tanh(pxg + dg);
            float og = fast_sigmoid(pxo + dz);
            c_reg = fg * c_reg + ig * gg;
            float hnew = og * fast_tanh(c_reg);

            if (step + 1 < SLEN) {
                int wb = p ^ 1;
#pragma unroll
                for (int rr = 0; rr < 8; rr++) {
                    uint32_t ra = wb ? rstore1[rr] : rstore0[rr];
                    asm volatile("st.shared::cluster.f32 [%0], %1;"
                                 :: "r"(ra), "f"(hnew) : "memory");
                }
                __syncwarp();
                if (tid < 16) {
                    uint32_t rm = wb ? rmb1 : rmb0;
                    asm volatile("mbarrier.arrive.release.cluster.shared::cluster.b64 _, [%0];"
                                 :: "r"(rm) : "memory");
                }
            }
            if (tid < 16) hout[s * HDIM + u] = hnew;
        }
        pxi = npxi; pxf = npxf; pxg = npxg; pxo = npxo;
    }
    asm volatile("barrier.cluster.arrive.aligned;" ::: "memory");
    asm volatile("barrier.cluster.wait.aligned;" ::: "memory");
    if (tid == 0) {
        asm volatile("mbarrier.inval.shared.b64 [%0];" :: "r"(mbar_sa) : "memory");
        asm volatile("mbarrier.inval.shared.b64 [%0];" :: "r"(mbar_sa + 8) : "memory");
    }
}

// ---------------- K3: feats ----------------
#define FEATS_SMEM ((512 * 33 + 8 * 512) * 4)
__global__ __launch_bounds__(256) void feats_kernel(const float* __restrict__ w_tag,
                                                    const float* __restrict__ b_tag)
{
    extern __shared__ float fs[];
    float* wt = fs;
    float* hs = fs + 512 * 33;

    int tid = threadIdx.x;
    for (int idx = tid; idx < NTAG * 512; idx += 256) {
        int t = idx >> 9;
        int k = idx & 511;
        wt[k * 33 + t] = w_tag[idx];
    }
    __syncthreads();

    int warp = tid >> 5, lane = tid & 31;
    float bias = b_tag[lane];
    float* hrow = hs + warp * 512;

#pragma unroll
    for (int p = 0; p < 4; p++) {
        int s = blockIdx.x * 32 + p * 8 + warp;
        float4* dsth = (float4*)hrow;
        const float4* hf4 = (const float4*)(g_h[0] + s * HDIM);
        const float4* hb4 = (const float4*)(g_h[1] + s * HDIM);
        dsth[lane] = hf4[lane];
        dsth[32 + lane] = hf4[32 + lane];
        dsth[64 + lane] = hb4[lane];
        dsth[96 + lane] = hb4[32 + lane];
        __syncwarp();
        float a0 = 0.f, a1 = 0.f, a2 = 0.f, a3 = 0.f;
#pragma unroll 8
        for (int k = 0; k < 512; k += 4) {
            float4 h = *(const float4*)(hrow + k);
            a0 += wt[(k + 0) * 33 + lane] * h.x;
            a1 += wt[(k + 1) * 33 + lane] * h.y;
            a2 += wt[(k + 2) * 33 + lane] * h.z;
            a3 += wt[(k + 3) * 33 + lane] * h.w;
        }
        g_feats[s * NTAG + lane] = (a0 + a1) + (a2 + a3) + bias;
        __syncwarp();
    }
}

// ---------------- K4a: Viterbi forward — 2 warps, 1 bar, shfl combine -------
// Thread (n=tid>>1, c=tid&1) owns a 16-wide chunk of tag n's row. Partials
// for tag n live in ADJACENT LANES of the same warp -> combine is one
// shfl_xor(1) + fmaxf (no second smem hop, no second bar). Double buffering
// makes one __syncthreads per iter sufficient. Exact: same elementwise adds,
// max regrouped 16+16 (order-invariant) => bitwise-identical fv stream.
__global__ void __launch_bounds__(64) vit_fwd_kernel(const float* __restrict__ trans,
                                                     float* __restrict__ out,
                                                     int out_size)
{
    __shared__ __align__(16) float fvs[2][32];
    __shared__ float term_s[32];
    int tid = threadIdx.x;
    int n = tid >> 1, c = tid & 1;

    float tr[16];
#pragma unroll
    for (int j = 0; j < 16; j++) tr[j] = trans[n * NTAG + c * 16 + j];

    float fv_n = (n == START_TAG) ? 0.f : NEGV;
    if (tid < 32) fvs[0][tid] = (tid == START_TAG) ? 0.f : NEGV;

    float f0 = g_feats[n];
    float f1 = g_feats[NTAG + n];
    __syncthreads();

    for (int t = 0; t < SLEN; t++) {
        int pb = t & 1;
        float f2 = (t + 2 < SLEN) ? g_feats[(t + 2) * NTAG + n] : 0.f;
        if (c == 0) g_fv[t * NTAG + n] = fv_n;     // entry value (off path)

        const float4* s4 = (const float4*)(fvs[pb] + c * 16);
        float4 x0 = s4[0], x1 = s4[1], x2 = s4[2], x3 = s4[3];
        float v0 = x0.x + tr[0],  v1 = x0.y + tr[1];
        float v2 = x0.z + tr[2],  v3 = x0.w + tr[3];
        float v4 = x1.x + tr[4],  v5 = x1.y + tr[5];
        float v6 = x1.z + tr[6],  v7 = x1.w + tr[7];
        float v8 = x2.x + tr[8],  v9 = x2.y + tr[9];
        float va = x2.z + tr[10], vb = x2.w + tr[11];
        float vc = x3.x + tr[12], vd = x3.y + tr[13];
        float ve = x3.z + tr[14], vf = x3.w + tr[15];
        float m = fmaxf(
            fmaxf(fmaxf(fmaxf(v0, v1), fmaxf(v2, v3)),
                  fmaxf(fmaxf(v4, v5), fmaxf(v6, v7))),
            fmaxf(fmaxf(fmaxf(v8, v9), fmaxf(va, vb)),
                  fmaxf(fmaxf(vc, vd), fmaxf(ve, vf))));
        // partner lane (same warp) holds the other 16-chunk's partial
        float best = fmaxf(m, __shfl_xor_sync(0xffffffffu, m, 1));
        float fv_new = best + f0;
        if (c == 0) fvs[pb ^ 1][n] = fv_new;
        __syncthreads();                 // single bar: write(b^1) vs next read

        fv_n = fv_new;
        f0 = f1; f1 = f2;
    }

    // terminal score + first-index argmax
    float term = fv_n + trans[STOP_TAG * NTAG + n];
    if (c == 0) term_s[n] = term;
    __syncthreads();
    if (tid < 32) {
        float bvv = term_s[tid];
        int bii = tid;
#pragma unroll
        for (int off = 16; off > 0; off >>= 1) {
            float ov = __shfl_down_sync(0xffffffffu, bvv, off);
            int oi = __shfl_down_sync(0xffffffffu, bii, off);
            if (ov > bvv || (ov == bvv && oi < bii)) { bvv = ov; bii = oi; }
        }
        if (tid == 0) {
            if (out_size > 0) out[0] = bvv;
            g_last = bii;
        }
    }
}

// ---------------- K4b: backpointers — PARALLEL over t ------------------------
__global__ __launch_bounds__(256) void vit_bp_kernel(const float* __restrict__ trans)
{
    __shared__ float trs[NTAG * NTAG];
    int tid = threadIdx.x;
#pragma unroll
    for (int i = tid; i < NTAG * NTAG; i += 256) trs[i] = trans[i];
    __syncthreads();

    int warp = tid >> 5, n = tid & 31;
    int t = blockIdx.x * 8 + warp;

    float fvv = g_fv[t * NTAG + n];
    float v[NTAG];
#pragma unroll
    for (int p = 0; p < NTAG; p++)
        v[p] = __shfl_sync(0xffffffffu, fvv, p) + trs[n * NTAG + p];
    float bv[16]; int bi[16];
#pragma unroll
    for (int q2 = 0; q2 < 16; q2++) {
        bool take = v[q2 + 16] > v[q2];
        bv[q2] = take ? v[q2 + 16] : v[q2];
        bi[q2] = take ? q2 + 16 : q2;
    }
#pragma unroll
    for (int st = 8; st > 0; st >>= 1) {
#pragma unroll
        for (int q2 = 0; q2 < 16; q2++) {
            if (q2 < st) {
                bool take = (bv[q2 + st] > bv[q2]) ||
                            (bv[q2 + st] == bv[q2] && bi[q2 + st] < bi[q2]);
                bv[q2] = take ? bv[q2 + st] : bv[q2];
                bi[q2] = take ? bi[q2 + st] : bi[q2];
            }
        }
    }
    g_bp[t * NTAG + n] = (unsigned char)bi[0];
}

// ---------------- K4c: backtrace (bp staged in smem) -------------------------
__global__ void __launch_bounds__(256) vit_trace_kernel(float* __restrict__ out,
                                                        int out_size)
{
    extern __shared__ unsigned char bps[];   // 64 KB
    int tid = threadIdx.x;
    const uint4* src = (const uint4*)g_bp;
    uint4* dst = (uint4*)bps;
#pragma unroll
    for (int i = 0; i < 16; i++) dst[tid + i * 256] = src[tid + i * 256];
    __syncthreads();
    if (tid == 0) {
        int tag = g_last;
        if (out_size > SLEN) out[SLEN] = (float)tag;
        for (int t = SLEN - 2; t >= 0; t--) {
            tag = bps[(t + 1) * NTAG + tag];
            if (1 + t < out_size) out[1 + t] = (float)tag;
        }
    }
}

// ---------------- launch -----------------------------------------------------
extern "C" void kernel_launch(void* const* d_in, const int* in_sizes, int n_in,
                              void* d_out, int out_size)
{
    const int*   sent   = (const int*)d_in[0];
    const float* embed  = (const float*)d_in[1];
    const float* w_ih_f = (const float*)d_in[2];
    const float* w_hh_f = (const float*)d_in[3];
    const float* b_f    = (const float*)d_in[4];
    const float* w_ih_b = (const float*)d_in[5];
    const float* w_hh_b = (const float*)d_in[6];
    const float* b_b    = (const float*)d_in[7];
    const float* w_tag  = (const float*)d_in[8];
    const float* b_tag  = (const float*)d_in[9];
    const float* trans  = (const float*)d_in[10];
    const float* h0     = (const float*)d_in[11];
    const float* c0     = (const float*)d_in[12];
    float* out = (float*)d_out;

    cudaFuncSetAttribute(lstm_kernel,
                         cudaFuncAttributeNonPortableClusterSizeAllowed, 1);
    cudaFuncSetAttribute(feats_kernel,
                         cudaFuncAttributeMaxDynamicSharedMemorySize, FEATS_SMEM);
    cudaFuncSetAttribute(vit_trace_kernel,
                         cudaFuncAttributeMaxDynamicSharedMemorySize, SLEN * NTAG);

    dim3 gg(SLEN / BM, (4 * HDIM) / BN, 2);
    px_gemm_kernel<<<gg, 256>>>(sent, embed, w_ih_f, b_f, w_ih_b, b_b);

    lstm_kernel<<<2 * CL, 256>>>(w_hh_f, w_hh_b, h0, c0);

    feats_kernel<<<SLEN / 32, 256, FEATS_SMEM>>>(w_tag, b_tag);

    vit_fwd_kernel<<<1, 64>>>(trans, out, out_size);
    vit_bp_kernel<<<SLEN / 8, 256>>>(trans);
    vit_trace_kernel<<<1, 256, SLEN * NTAG>>>(out, out_size);
}